// round 15
// baseline (speedup 1.0000x reference)
#include <cuda_runtime.h>
#include <cuda_bf16.h>
#include <cstdint>

#define N_NODES 10000
#define N_EDGES 160000

// ---------------- device scratch (static; no allocations) ----------------
__device__ float g_ux0[N_NODES * 128];   // up-projected scalars   [n][v]
__device__ float g_ux1[N_NODES * 384];   // up-projected vectors   [n][v][m]
__device__ float g_msg0[N_NODES * 256];  // scalar messages        [n][u]
__device__ float g_msg1[N_NODES * 768];  // vector messages        [n][u][m]

__device__ __forceinline__ float act(float y) {
    return 1.679177f * y / (1.0f + __expf(-y));   // SILU_2MOM * silu
}

__device__ __forceinline__ void red4(float* p, float a, float b, float c, float d) {
    asm volatile("red.global.add.v4.f32 [%0], {%1,%2,%3,%4};"
                 :: "l"(p), "f"(a), "f"(b), "f"(c), "f"(d) : "memory");
}

// pack two fp32 into bf16x2 hi + residual bf16x2 lo
__device__ __forceinline__ void packhl(float x, float y, uint32_t& hi, uint32_t& lo) {
    __nv_bfloat162 h = __floats2bfloat162_rn(x, y);
    float lx = x - __bfloat162float(__low2bfloat16(h));
    float ly = y - __bfloat162float(__high2bfloat16(h));
    __nv_bfloat162 l = __floats2bfloat162_rn(lx, ly);
    hi = *reinterpret_cast<uint32_t*>(&h);
    lo = *reinterpret_cast<uint32_t*>(&l);
}

// one m16n8k16 bf16 mma, C += A*B
__device__ __forceinline__ void mma1(float* C, const uint32_t* a, uint32_t b0, uint32_t b1) {
    asm volatile(
        "mma.sync.aligned.m16n8k16.row.col.f32.bf16.bf16.f32 "
        "{%0,%1,%2,%3}, {%4,%5,%6,%7}, {%8,%9}, {%0,%1,%2,%3};"
        : "+f"(C[0]), "+f"(C[1]), "+f"(C[2]), "+f"(C[3])
        : "r"(a[0]), "r"(a[1]), "r"(a[2]), "r"(a[3]), "r"(b0), "r"(b1));
}

// 16(edges) x 64(out) x 64(k) GEMM per warp, bf16 hi/lo split (3 passes).
__device__ __forceinline__ void gemm64(const __nv_bfloat16* __restrict__ bHi,
                                       const __nv_bfloat16* __restrict__ bLo,
                                       const uint32_t* ahi, const uint32_t* alo,
                                       int lane, float C[8][4]) {
    const int bn = lane >> 2;
    const int bk = (lane & 3) * 2;
#pragma unroll
    for (int j = 0; j < 8; j++) {
#pragma unroll
        for (int kt = 0; kt < 4; kt++) {
            const __nv_bfloat16* ph = bHi + (8 * j + bn) * 72 + 16 * kt + bk;
            const __nv_bfloat16* pl = bLo + (8 * j + bn) * 72 + 16 * kt + bk;
            uint32_t bh0 = *(const uint32_t*)ph;
            uint32_t bh1 = *(const uint32_t*)(ph + 8);
            uint32_t bl0 = *(const uint32_t*)pl;
            uint32_t bl1 = *(const uint32_t*)(pl + 8);
            mma1(C[j], ahi + kt * 4, bh0, bh1);
            mma1(C[j], ahi + kt * 4, bl0, bl1);
            mma1(C[j], alo + kt * 4, bh0, bh1);
        }
    }
}

// build transposed bf16 hi/lo weight tile: B[n=c][k] = W[k][coff+c], 64x64, stride 72
__device__ __forceinline__ void build_w(const float* __restrict__ W, int ldw, int coff,
                                        __nv_bfloat16* bHi, __nv_bfloat16* bLo, int t) {
    for (int i = t; i < 4096; i += 256) {
        int k = i >> 6, c = i & 63;
        float w = W[k * ldw + coff + c];
        __nv_bfloat16 h = __float2bfloat16(w);
        float lo = w - __bfloat162float(h);
        bHi[c * 72 + k] = h;
        bLo[c * 72 + k] = __float2bfloat16(lo);
    }
}

// W4 chunk with paired-column remap:
//  q<4 : cols 0..31 = w1[32q + c],  cols 32..63 = w2[32q + (c-32)]
//  q>=4: cols 0..31 = w3[32(q-4)+c], cols 32..63 = w4[32(q-4)+(c-32)]
__device__ __forceinline__ void build_w4(const float* __restrict__ W4, int q,
                                         __nv_bfloat16* bHi, __nv_bfloat16* bLo, int t) {
    const int base1 = (q < 4) ? 32 * q : 256 + 32 * (q - 4);
    for (int i = t; i < 4096; i += 256) {
        int k = i >> 6, c = i & 63;
        int col = (c < 32) ? (base1 + c) : (base1 + 128 + (c - 32));
        float w = W4[k * 512 + col];
        __nv_bfloat16 h = __float2bfloat16(w);
        float lo = w - __bfloat162float(h);
        bHi[c * 72 + k] = h;
        bLo[c * 72 + k] = __float2bfloat16(lo);
    }
}

// ---------------- zero message buffers ----------------
__global__ void zero_kernel() {
    int i = blockIdx.x * blockDim.x + threadIdx.x;
    const float4 z = make_float4(0.f, 0.f, 0.f, 0.f);
    if (i < 640000) {
        ((float4*)g_msg0)[i] = z;
    } else if (i < 2560000) {
        ((float4*)g_msg1)[i - 640000] = z;
    }
}

// ---------------- node up-projection (smem-staged weight chunks) ----------------
// 256 threads, 16 nodes/block; warp w owns nodes {2w, 2w+1}; lane owns 4 channels.
#define UP_SMEM (65536)
__global__ __launch_bounds__(256) void up_kernel(const float* __restrict__ nf,
                                                 const float* __restrict__ W0,
                                                 const float* __restrict__ W1) {
    extern __shared__ float smu[];
    float* sX = smu;             // 8192 floats
    float* sW = smu + 8192;      // 8192 floats
    const int t = threadIdx.x;
    const int n0 = blockIdx.x * 16;
    for (int i = t; i < 16 * 512; i += 256) sX[i] = nf[n0 * 512 + i];

    const int w = t >> 5, lane = t & 31;
    const int v0 = lane * 4;
    const float* xA = &sX[(2 * w) * 512];
    const float* xB = &sX[(2 * w + 1) * 512];

    float a0[2][4];
    float a1[2][4][3];
#pragma unroll
    for (int n = 0; n < 2; n++)
#pragma unroll
        for (int j = 0; j < 4; j++) {
            a0[n][j] = 0.f;
            a1[n][j][0] = 0.f; a1[n][j][1] = 0.f; a1[n][j][2] = 0.f;
        }

    for (int ci = 0; ci < 4; ci++) {
        const int u0 = ci * 32;
        __syncthreads();
        for (int i = t; i < 8192; i += 256) {
            int r = i >> 8, c = i & 255;
            sW[i] = (c < 128) ? W0[(u0 + r) * 128 + c] : W1[(u0 + r) * 128 + (c - 128)];
        }
        __syncthreads();
#pragma unroll 4
        for (int u = 0; u < 32; u++) {
            const float4 w0 = *(const float4*)&sW[u * 256 + v0];
            const float4 w1 = *(const float4*)&sW[u * 256 + 128 + v0];
            const float wv0[4] = {w0.x, w0.y, w0.z, w0.w};
            const float wv1[4] = {w1.x, w1.y, w1.z, w1.w};
            const int uu = u0 + u;
#pragma unroll
            for (int n = 0; n < 2; n++) {
                const float* x = n ? xB : xA;
                const float x0 = x[uu];
                const float xa = x[128 + uu * 3 + 0];
                const float xb = x[128 + uu * 3 + 1];
                const float xc = x[128 + uu * 3 + 2];
#pragma unroll
                for (int j = 0; j < 4; j++) {
                    a0[n][j] += x0 * wv0[j];
                    a1[n][j][0] += xa * wv1[j];
                    a1[n][j][1] += xb * wv1[j];
                    a1[n][j][2] += xc * wv1[j];
                }
            }
        }
    }

    const float s = 0.08838834764831845f;  // 1/sqrt(128)
#pragma unroll
    for (int n = 0; n < 2; n++) {
        const int gn = n0 + 2 * w + n;
        float4 o0 = make_float4(a0[n][0] * s, a0[n][1] * s, a0[n][2] * s, a0[n][3] * s);
        *(float4*)&g_ux0[gn * 128 + v0] = o0;
        float* dst = &g_ux1[gn * 384 + v0 * 3];
        float4 p0 = make_float4(a1[n][0][0] * s, a1[n][0][1] * s, a1[n][0][2] * s, a1[n][1][0] * s);
        float4 p1 = make_float4(a1[n][1][1] * s, a1[n][1][2] * s, a1[n][2][0] * s, a1[n][2][1] * s);
        float4 p2 = make_float4(a1[n][2][2] * s, a1[n][3][0] * s, a1[n][3][1] * s, a1[n][3][2] * s);
        *(float4*)(dst + 0) = p0;
        *(float4*)(dst + 4) = p1;
        *(float4*)(dst + 8) = p2;
    }
}

// ---------------- fused edge MLP (mma.sync bf16 hi/lo) + tensor product + scatter ----
#define EDGE_SMEM 80896

__global__ __launch_bounds__(256, 2) void edge_kernel(
    const float* __restrict__ edge_attrs, const float* __restrict__ edge_feats,
    const int* __restrict__ edge_index,
    const float* __restrict__ Wm1, const float* __restrict__ Wm2,
    const float* __restrict__ Wm3, const float* __restrict__ Wm4)
{
    extern __shared__ __align__(16) char sm[];
    __nv_bfloat16* bHi0 = (__nv_bfloat16*)(sm + 0);
    __nv_bfloat16* bLo0 = (__nv_bfloat16*)(sm + 9216);
    __nv_bfloat16* bHi1 = (__nv_bfloat16*)(sm + 18432);
    __nv_bfloat16* bLo1 = (__nv_bfloat16*)(sm + 27648);
    float* sTP = (float*)(sm + 36864);   // stride 68 per edge
    float* sEF = (float*)(sm + 71680);
    float* sW1 = (float*)(sm + 75776);
    float* sY0 = (float*)(sm + 77824);
    float* sY1 = (float*)(sm + 78336);
    int*  sSnd = (int*)(sm + 79872);
    int*  sRcv = (int*)(sm + 80384);

    const int t = threadIdx.x;
    const int w = t >> 5;
    const int lane = t & 31;
    const int e0 = blockIdx.x * 128;

    for (int i = t; i < 1024; i += 256) sEF[i] = edge_feats[e0 * 8 + i];
    for (int i = t; i < 512; i += 256) sW1[i] = Wm1[i];
    if (t < 128) {
        sSnd[t] = edge_index[e0 + t];
        sRcv[t] = edge_index[N_EDGES + e0 + t];
        const float4 a = *(const float4*)&edge_attrs[(e0 + t) * 4];
        sY0[t] = a.x;
        sY1[t * 3 + 0] = a.y; sY1[t * 3 + 1] = a.z; sY1[t * 3 + 2] = a.w;
    }
    build_w(Wm2, 64, 0, bHi0, bLo0, t);
    build_w(Wm3, 64, 0, bHi1, bLo1, t);
    __syncthreads();

    const int rl = lane >> 2;
    const int cb = (lane & 3) * 2;

    // ---- layer 1: 8 -> 64, straight into A fragments ----
    uint32_t ahi[16], alo[16];
    {
        float2 h0[8], h1[8];
#pragma unroll
        for (int m = 0; m < 8; m++) { h0[m] = make_float2(0.f, 0.f); h1[m] = make_float2(0.f, 0.f); }
        const float* efA = &sEF[(w * 16 + rl) * 8];
        const float* efB = &sEF[(w * 16 + rl + 8) * 8];
#pragma unroll
        for (int k = 0; k < 8; k++) {
            const float ea_ = efA[k], eb_ = efB[k];
#pragma unroll
            for (int m = 0; m < 8; m++) {
                const float2 w2 = *(const float2*)&sW1[k * 64 + 8 * m + cb];
                h0[m].x += ea_ * w2.x; h0[m].y += ea_ * w2.y;
                h1[m].x += eb_ * w2.x; h1[m].y += eb_ * w2.y;
            }
        }
        const float s1 = 0.35355339059327373f;  // 1/sqrt(8)
#pragma unroll
        for (int m = 0; m < 8; m++) {
            const int base = (m >> 1) * 4 + (m & 1) * 2;
            packhl(act(h0[m].x * s1), act(h0[m].y * s1), ahi[base], alo[base]);
            packhl(act(h1[m].x * s1), act(h1[m].y * s1), ahi[base + 1], alo[base + 1]);
        }
    }

    float C[8][4];
    // ---- layer 2 ----
#pragma unroll
    for (int j = 0; j < 8; j++) { C[j][0] = C[j][1] = C[j][2] = C[j][3] = 0.f; }
    gemm64(bHi0, bLo0, ahi, alo, lane, C);
#pragma unroll
    for (int j = 0; j < 8; j++) {
        const int base = (j >> 1) * 4 + (j & 1) * 2;
        packhl(act(C[j][0] * 0.125f), act(C[j][1] * 0.125f), ahi[base], alo[base]);
        packhl(act(C[j][2] * 0.125f), act(C[j][3] * 0.125f), ahi[base + 1], alo[base + 1]);
    }

    // ---- layer 3 ----
#pragma unroll
    for (int j = 0; j < 8; j++) { C[j][0] = C[j][1] = C[j][2] = C[j][3] = 0.f; }
    gemm64(bHi1, bLo1, ahi, alo, lane, C);
#pragma unroll
    for (int j = 0; j < 8; j++) {
        const int base = (j >> 1) * 4 + (j & 1) * 2;
        packhl(act(C[j][0] * 0.125f), act(C[j][1] * 0.125f), ahi[base], alo[base]);
        packhl(act(C[j][2] * 0.125f), act(C[j][3] * 0.125f), ahi[base + 1], alo[base + 1]);
    }

    __syncthreads();
    build_w4(Wm4, 0, bHi0, bLo0, t);
    build_w4(Wm4, 1, bHi1, bLo1, t);
    __syncthreads();

    // ---- layer 4 (8 paired chunks) + tensor product + scatter ----
    const float inv_sqrt3 = 0.5773502691896258f;
    const int eScat = w * 16 + (lane & 15);
    const int half = lane >> 4;
    const int snd = sSnd[eScat], rcv = sRcv[eScat];
    const float y0 = sY0[eScat];
    const float ya = sY1[eScat * 3], yb = sY1[eScat * 3 + 1], yc = sY1[eScat * 3 + 2];
    const int rowA = w * 16 + rl, rowB = rowA + 8;
    const float* tp = &sTP[eScat * 68 + half * 16];

    for (int q = 0; q < 8; q++) {
#pragma unroll
        for (int j = 0; j < 8; j++) { C[j][0] = C[j][1] = C[j][2] = C[j][3] = 0.f; }
        if (q & 1) gemm64(bHi1, bLo1, ahi, alo, lane, C);
        else       gemm64(bHi0, bLo0, ahi, alo, lane, C);

        // stage to warp-local sTP rows with the 1/sqrt(64) scale applied ONCE here
#pragma unroll
        for (int j = 0; j < 8; j++) {
            *(float2*)&sTP[rowA * 68 + 8 * j + cb] = make_float2(C[j][0] * 0.125f, C[j][1] * 0.125f);
            *(float2*)&sTP[rowB * 68 + 8 * j + cb] = make_float2(C[j][2] * 0.125f, C[j][3] * 0.125f);
        }
        __syncwarp();

        if (q < 4) {
            const int qch = 32 * q + half * 16;
#pragma unroll
            for (int jj = 0; jj < 16; jj += 4) {
                const float4 va = *(const float4*)(tp + jj);        // w1
                const float4 vb = *(const float4*)(tp + 32 + jj);   // w2
                const float4 s0 = *(const float4*)&g_ux0[snd * 128 + qch + jj];
                red4(&g_msg0[rcv * 256 + qch + jj],
                     va.x * s0.x * y0, va.y * s0.y * y0,
                     va.z * s0.z * y0, va.w * s0.w * y0);
                const float c0v = vb.x * s0.x, c1v = vb.y * s0.y;
                const float c2v = vb.z * s0.z, c3v = vb.w * s0.w;
                float* dst = &g_msg1[rcv * 768 + (qch + jj) * 3];
                red4(dst + 0, c0v * ya, c0v * yb, c0v * yc, c1v * ya);
                red4(dst + 4, c1v * yb, c1v * yc, c2v * ya, c2v * yb);
                red4(dst + 8, c2v * yc, c3v * ya, c3v * yb, c3v * yc);
            }
        } else {
            const int qch = 32 * (q - 4) + half * 16;
#pragma unroll
            for (int jj = 0; jj < 16; jj += 4) {
                const float4 va = *(const float4*)(tp + jj);        // w3
                const float4 vb = *(const float4*)(tp + 32 + jj);   // w4
                const float* s1 = &g_ux1[snd * 384 + (qch + jj) * 3];
                const float4 a = *(const float4*)(s1 + 0);
                const float4 b = *(const float4*)(s1 + 4);
                const float4 c = *(const float4*)(s1 + 8);
                float* dst = &g_msg1[rcv * 768 + 384 + (qch + jj) * 3];
                red4(dst + 0, va.x * a.x * y0, va.x * a.y * y0, va.x * a.z * y0, va.y * a.w * y0);
                red4(dst + 4, va.y * b.x * y0, va.y * b.y * y0, va.z * b.z * y0, va.z * b.w * y0);
                red4(dst + 8, va.z * c.x * y0, va.w * c.y * y0, va.w * c.z * y0, va.w * c.w * y0);
                const float d0 = a.x * ya + a.y * yb + a.z * yc;
                const float d1 = a.w * ya + b.x * yb + b.y * yc;
                const float d2 = b.z * ya + b.w * yb + c.x * yc;
                const float d3 = c.y * ya + c.z * yb + c.w * yc;
                red4(&g_msg0[rcv * 256 + 128 + qch + jj],
                     vb.x * d0 * inv_sqrt3, vb.y * d1 * inv_sqrt3,
                     vb.z * d2 * inv_sqrt3, vb.w * d3 * inv_sqrt3);
            }
        }

        __syncthreads();   // all warps done reading buf[q&1]; prior builds visible
        if (q < 6) {
            if (q & 1) build_w4(Wm4, q + 2, bHi1, bLo1, t);
            else       build_w4(Wm4, q + 2, bHi0, bLo0, t);
        }
    }
}

// ---------------- output linear (smem-staged weight chunks) ----------------
#define OUT_SMEM (98304)
__global__ __launch_bounds__(256) void out_kernel(const float* __restrict__ Wo0,
                                                  const float* __restrict__ Wo1,
                                                  float* __restrict__ out) {
    extern __shared__ float smo[];
    float* sX = smo;              // 16384 floats
    float* sW = smo + 16384;      // 8192 floats
    const int t = threadIdx.x;
    const int n0 = blockIdx.x * 16;
    for (int i = t; i < 16 * 1024; i += 256) {
        const int n = i >> 10, c = i & 1023;
        const int gn = n0 + n;
        sX[i] = (c < 256) ? g_msg0[gn * 256 + c] : g_msg1[gn * 768 + (c - 256)];
    }

    const int w = t >> 5, lane = t & 31;
    const int v0 = lane * 4;
    const float* xA = &sX[(2 * w) * 1024];
    const float* xB = &sX[(2 * w + 1) * 1024];

    float a0[2][4];
    float a1[2][4][3];
#pragma unroll
    for (int n = 0; n < 2; n++)
#pragma unroll
        for (int j = 0; j < 4; j++) {
            a0[n][j] = 0.f;
            a1[n][j][0] = 0.f; a1[n][j][1] = 0.f; a1[n][j][2] = 0.f;
        }

    for (int ci = 0; ci < 8; ci++) {
        const int u0 = ci * 32;
        __syncthreads();
        for (int i = t; i < 8192; i += 256) {
            int r = i >> 8, c = i & 255;
            sW[i] = (c < 128) ? Wo0[(u0 + r) * 128 + c] : Wo1[(u0 + r) * 128 + (c - 128)];
        }
        __syncthreads();
#pragma unroll 4
        for (int u = 0; u < 32; u++) {
            const float4 w0 = *(const float4*)&sW[u * 256 + v0];
            const float4 w1 = *(const float4*)&sW[u * 256 + 128 + v0];
            const float wv0[4] = {w0.x, w0.y, w0.z, w0.w};
            const float wv1[4] = {w1.x, w1.y, w1.z, w1.w};
            const int uu = u0 + u;
#pragma unroll
            for (int n = 0; n < 2; n++) {
                const float* x = n ? xB : xA;
                const float m0 = x[uu];
                const float ma = x[256 + uu * 3 + 0];
                const float mb = x[256 + uu * 3 + 1];
                const float mc = x[256 + uu * 3 + 2];
#pragma unroll
                for (int j = 0; j < 4; j++) {
                    a0[n][j] += m0 * wv0[j];
                    a1[n][j][0] += ma * wv1[j];
                    a1[n][j][1] += mb * wv1[j];
                    a1[n][j][2] += mc * wv1[j];
                }
            }
        }
    }

    const float s = 1.0f / 160.0f;  // (1/sqrt(256)) / AVG_NUM_NEIGHBORS
#pragma unroll
    for (int n = 0; n < 2; n++) {
        const int gn = n0 + 2 * w + n;
        float4 o0 = make_float4(a0[n][0] * s, a0[n][1] * s, a0[n][2] * s, a0[n][3] * s);
        *(float4*)&out[gn * 512 + v0] = o0;
        float* dst = &out[gn * 512 + 128 + v0 * 3];
        float4 p0 = make_float4(a1[n][0][0] * s, a1[n][0][1] * s, a1[n][0][2] * s, a1[n][1][0] * s);
        float4 p1 = make_float4(a1[n][1][1] * s, a1[n][1][2] * s, a1[n][2][0] * s, a1[n][2][1] * s);
        float4 p2 = make_float4(a1[n][2][2] * s, a1[n][3][0] * s, a1[n][3][1] * s, a1[n][3][2] * s);
        *(float4*)(dst + 0) = p0;
        *(float4*)(dst + 4) = p1;
        *(float4*)(dst + 8) = p2;
    }
}

// ---------------- launch ----------------
extern "C" void kernel_launch(void* const* d_in, const int* in_sizes, int n_in,
                              void* d_out, int out_size) {
    const float* nf  = (const float*)d_in[0];
    const float* ea  = (const float*)d_in[1];
    const float* ef  = (const float*)d_in[2];
    const int*   ei  = (const int*)d_in[3];
    const float* Wu0 = (const float*)d_in[4];
    const float* Wu1 = (const float*)d_in[5];
    const float* Wm1 = (const float*)d_in[6];
    const float* Wm2 = (const float*)d_in[7];
    const float* Wm3 = (const float*)d_in[8];
    const float* Wm4 = (const float*)d_in[9];
    const float* Wo0 = (const float*)d_in[10];
    const float* Wo1 = (const float*)d_in[11];
    float* out = (float*)d_out;

    cudaFuncSetAttribute(edge_kernel, cudaFuncAttributeMaxDynamicSharedMemorySize, EDGE_SMEM);
    cudaFuncSetAttribute(out_kernel, cudaFuncAttributeMaxDynamicSharedMemorySize, OUT_SMEM);
    cudaFuncSetAttribute(up_kernel, cudaFuncAttributeMaxDynamicSharedMemorySize, UP_SMEM);

    zero_kernel<<<10000, 256>>>();
    up_kernel<<<625, 256, UP_SMEM>>>(nf, Wu0, Wu1);
    edge_kernel<<<1250, 256, EDGE_SMEM>>>(ea, ef, ei, Wm1, Wm2, Wm3, Wm4);
    out_kernel<<<625, 256, OUT_SMEM>>>(Wo0, Wo1, out);
}

// round 16
// speedup vs baseline: 1.0041x; 1.0041x over previous
#include <cuda_runtime.h>
#include <cuda_bf16.h>
#include <cstdint>

#define N_NODES 10000
#define N_EDGES 160000

// ---------------- device scratch (static; no allocations) ----------------
__device__ float g_ux0[N_NODES * 128];   // up-projected scalars   [n][v]
__device__ float g_ux1[N_NODES * 384];   // up-projected vectors   [n][v][m]
__device__ float g_msg0[N_NODES * 256];  // scalar messages        [n][u]
__device__ float g_msg1[N_NODES * 768];  // vector messages        [n][u][m]

__device__ __forceinline__ float act(float y) {
    return 1.679177f * y / (1.0f + __expf(-y));   // SILU_2MOM * silu
}

__device__ __forceinline__ void red4(float* p, float a, float b, float c, float d) {
    asm volatile("red.global.add.v4.f32 [%0], {%1,%2,%3,%4};"
                 :: "l"(p), "f"(a), "f"(b), "f"(c), "f"(d) : "memory");
}

// pack two fp32 into bf16x2 hi + residual bf16x2 lo
__device__ __forceinline__ void packhl(float x, float y, uint32_t& hi, uint32_t& lo) {
    __nv_bfloat162 h = __floats2bfloat162_rn(x, y);
    float lx = x - __bfloat162float(__low2bfloat16(h));
    float ly = y - __bfloat162float(__high2bfloat16(h));
    __nv_bfloat162 l = __floats2bfloat162_rn(lx, ly);
    hi = *reinterpret_cast<uint32_t*>(&h);
    lo = *reinterpret_cast<uint32_t*>(&l);
}

// one m16n8k16 bf16 mma, C += A*B
__device__ __forceinline__ void mma1(float* C, const uint32_t* a, uint32_t b0, uint32_t b1) {
    asm volatile(
        "mma.sync.aligned.m16n8k16.row.col.f32.bf16.bf16.f32 "
        "{%0,%1,%2,%3}, {%4,%5,%6,%7}, {%8,%9}, {%0,%1,%2,%3};"
        : "+f"(C[0]), "+f"(C[1]), "+f"(C[2]), "+f"(C[3])
        : "r"(a[0]), "r"(a[1]), "r"(a[2]), "r"(a[3]), "r"(b0), "r"(b1));
}

// 16(edges) x 64(out) x 64(k) GEMM per warp, bf16 hi/lo split (3 passes).
__device__ __forceinline__ void gemm64(const __nv_bfloat16* __restrict__ bHi,
                                       const __nv_bfloat16* __restrict__ bLo,
                                       const uint32_t* ahi, const uint32_t* alo,
                                       int lane, float C[8][4]) {
    const int bn = lane >> 2;
    const int bk = (lane & 3) * 2;
#pragma unroll
    for (int j = 0; j < 8; j++) {
#pragma unroll
        for (int kt = 0; kt < 4; kt++) {
            const __nv_bfloat16* ph = bHi + (8 * j + bn) * 72 + 16 * kt + bk;
            const __nv_bfloat16* pl = bLo + (8 * j + bn) * 72 + 16 * kt + bk;
            uint32_t bh0 = *(const uint32_t*)ph;
            uint32_t bh1 = *(const uint32_t*)(ph + 8);
            uint32_t bl0 = *(const uint32_t*)pl;
            uint32_t bl1 = *(const uint32_t*)(pl + 8);
            mma1(C[j], ahi + kt * 4, bh0, bh1);
            mma1(C[j], ahi + kt * 4, bl0, bl1);
            mma1(C[j], alo + kt * 4, bh0, bh1);
        }
    }
}

// build transposed bf16 hi/lo weight tile: B[n=c][k] = W[k][coff+c], 64x64, stride 72
__device__ __forceinline__ void build_w(const float* __restrict__ W, int ldw, int coff,
                                        __nv_bfloat16* bHi, __nv_bfloat16* bLo, int t) {
    for (int i = t; i < 4096; i += 256) {
        int k = i >> 6, c = i & 63;
        float w = W[k * ldw + coff + c];
        __nv_bfloat16 h = __float2bfloat16(w);
        float lo = w - __bfloat162float(h);
        bHi[c * 72 + k] = h;
        bLo[c * 72 + k] = __float2bfloat16(lo);
    }
}

// W4 chunk with paired-column remap:
//  q<4 : cols 0..31 = w1[32q + c],  cols 32..63 = w2[32q + (c-32)]
//  q>=4: cols 0..31 = w3[32(q-4)+c], cols 32..63 = w4[32(q-4)+(c-32)]
__device__ __forceinline__ void build_w4(const float* __restrict__ W4, int q,
                                         __nv_bfloat16* bHi, __nv_bfloat16* bLo, int t) {
    const int base1 = (q < 4) ? 32 * q : 256 + 32 * (q - 4);
    for (int i = t; i < 4096; i += 256) {
        int k = i >> 6, c = i & 63;
        int col = (c < 32) ? (base1 + c) : (base1 + 128 + (c - 32));
        float w = W4[k * 512 + col];
        __nv_bfloat16 h = __float2bfloat16(w);
        float lo = w - __bfloat162float(h);
        bHi[c * 72 + k] = h;
        bLo[c * 72 + k] = __float2bfloat16(lo);
    }
}

// ---------------- zero message buffers ----------------
__global__ void zero_kernel() {
    int i = blockIdx.x * blockDim.x + threadIdx.x;
    const float4 z = make_float4(0.f, 0.f, 0.f, 0.f);
    if (i < 640000) {
        ((float4*)g_msg0)[i] = z;
    } else if (i < 2560000) {
        ((float4*)g_msg1)[i - 640000] = z;
    }
}

// ---------------- node up-projection (smem-staged weight chunks) ----------------
// 256 threads, 16 nodes/block; warp w owns nodes {2w, 2w+1}; lane owns 4 channels.
#define UP_SMEM (65536)
__global__ __launch_bounds__(256) void up_kernel(const float* __restrict__ nf,
                                                 const float* __restrict__ W0,
                                                 const float* __restrict__ W1) {
    extern __shared__ float smu[];
    float* sX = smu;             // 8192 floats
    float* sW = smu + 8192;      // 8192 floats
    const int t = threadIdx.x;
    const int n0 = blockIdx.x * 16;
    for (int i = t; i < 16 * 512; i += 256) sX[i] = nf[n0 * 512 + i];

    const int w = t >> 5, lane = t & 31;
    const int v0 = lane * 4;
    const float* xA = &sX[(2 * w) * 512];
    const float* xB = &sX[(2 * w + 1) * 512];

    float a0[2][4];
    float a1[2][4][3];
#pragma unroll
    for (int n = 0; n < 2; n++)
#pragma unroll
        for (int j = 0; j < 4; j++) {
            a0[n][j] = 0.f;
            a1[n][j][0] = 0.f; a1[n][j][1] = 0.f; a1[n][j][2] = 0.f;
        }

    for (int ci = 0; ci < 4; ci++) {
        const int u0 = ci * 32;
        __syncthreads();
        for (int i = t; i < 8192; i += 256) {
            int r = i >> 8, c = i & 255;
            sW[i] = (c < 128) ? W0[(u0 + r) * 128 + c] : W1[(u0 + r) * 128 + (c - 128)];
        }
        __syncthreads();
#pragma unroll 4
        for (int u = 0; u < 32; u++) {
            const float4 w0 = *(const float4*)&sW[u * 256 + v0];
            const float4 w1 = *(const float4*)&sW[u * 256 + 128 + v0];
            const float wv0[4] = {w0.x, w0.y, w0.z, w0.w};
            const float wv1[4] = {w1.x, w1.y, w1.z, w1.w};
            const int uu = u0 + u;
#pragma unroll
            for (int n = 0; n < 2; n++) {
                const float* x = n ? xB : xA;
                const float x0 = x[uu];
                const float xa = x[128 + uu * 3 + 0];
                const float xb = x[128 + uu * 3 + 1];
                const float xc = x[128 + uu * 3 + 2];
#pragma unroll
                for (int j = 0; j < 4; j++) {
                    a0[n][j] += x0 * wv0[j];
                    a1[n][j][0] += xa * wv1[j];
                    a1[n][j][1] += xb * wv1[j];
                    a1[n][j][2] += xc * wv1[j];
                }
            }
        }
    }

    const float s = 0.08838834764831845f;  // 1/sqrt(128)
#pragma unroll
    for (int n = 0; n < 2; n++) {
        const int gn = n0 + 2 * w + n;
        float4 o0 = make_float4(a0[n][0] * s, a0[n][1] * s, a0[n][2] * s, a0[n][3] * s);
        *(float4*)&g_ux0[gn * 128 + v0] = o0;
        float* dst = &g_ux1[gn * 384 + v0 * 3];
        float4 p0 = make_float4(a1[n][0][0] * s, a1[n][0][1] * s, a1[n][0][2] * s, a1[n][1][0] * s);
        float4 p1 = make_float4(a1[n][1][1] * s, a1[n][1][2] * s, a1[n][2][0] * s, a1[n][2][1] * s);
        float4 p2 = make_float4(a1[n][2][2] * s, a1[n][3][0] * s, a1[n][3][1] * s, a1[n][3][2] * s);
        *(float4*)(dst + 0) = p0;
        *(float4*)(dst + 4) = p1;
        *(float4*)(dst + 8) = p2;
    }
}

// ---------------- fused edge MLP (mma.sync bf16 hi/lo) + tensor product + scatter ----
#define EDGE_SMEM 80896

__global__ __launch_bounds__(256, 2) void edge_kernel(
    const float* __restrict__ edge_attrs, const float* __restrict__ edge_feats,
    const int* __restrict__ edge_index,
    const float* __restrict__ Wm1, const float* __restrict__ Wm2,
    const float* __restrict__ Wm3, const float* __restrict__ Wm4)
{
    extern __shared__ __align__(16) char sm[];
    __nv_bfloat16* bHi0 = (__nv_bfloat16*)(sm + 0);
    __nv_bfloat16* bLo0 = (__nv_bfloat16*)(sm + 9216);
    __nv_bfloat16* bHi1 = (__nv_bfloat16*)(sm + 18432);
    __nv_bfloat16* bLo1 = (__nv_bfloat16*)(sm + 27648);
    float* sTP = (float*)(sm + 36864);   // stride 68 per edge
    float* sEF = (float*)(sm + 71680);
    float* sW1 = (float*)(sm + 75776);
    float* sY0 = (float*)(sm + 77824);
    float* sY1 = (float*)(sm + 78336);
    int*  sSnd = (int*)(sm + 79872);
    int*  sRcv = (int*)(sm + 80384);

    const int t = threadIdx.x;
    const int w = t >> 5;
    const int lane = t & 31;
    const int e0 = blockIdx.x * 128;

    for (int i = t; i < 1024; i += 256) sEF[i] = edge_feats[e0 * 8 + i];
    for (int i = t; i < 512; i += 256) sW1[i] = Wm1[i];
    if (t < 128) {
        sSnd[t] = edge_index[e0 + t];
        sRcv[t] = edge_index[N_EDGES + e0 + t];
        const float4 a = *(const float4*)&edge_attrs[(e0 + t) * 4];
        sY0[t] = a.x;
        sY1[t * 3 + 0] = a.y; sY1[t * 3 + 1] = a.z; sY1[t * 3 + 2] = a.w;
    }
    build_w(Wm2, 64, 0, bHi0, bLo0, t);
    build_w(Wm3, 64, 0, bHi1, bLo1, t);
    __syncthreads();

    const int rl = lane >> 2;
    const int cb = (lane & 3) * 2;

    // ---- layer 1: 8 -> 64, straight into A fragments ----
    uint32_t ahi[16], alo[16];
    {
        float2 h0[8], h1[8];
#pragma unroll
        for (int m = 0; m < 8; m++) { h0[m] = make_float2(0.f, 0.f); h1[m] = make_float2(0.f, 0.f); }
        const float* efA = &sEF[(w * 16 + rl) * 8];
        const float* efB = &sEF[(w * 16 + rl + 8) * 8];
#pragma unroll
        for (int k = 0; k < 8; k++) {
            const float ea_ = efA[k], eb_ = efB[k];
#pragma unroll
            for (int m = 0; m < 8; m++) {
                const float2 w2 = *(const float2*)&sW1[k * 64 + 8 * m + cb];
                h0[m].x += ea_ * w2.x; h0[m].y += ea_ * w2.y;
                h1[m].x += eb_ * w2.x; h1[m].y += eb_ * w2.y;
            }
        }
        const float s1 = 0.35355339059327373f;  // 1/sqrt(8)
#pragma unroll
        for (int m = 0; m < 8; m++) {
            const int base = (m >> 1) * 4 + (m & 1) * 2;
            packhl(act(h0[m].x * s1), act(h0[m].y * s1), ahi[base], alo[base]);
            packhl(act(h1[m].x * s1), act(h1[m].y * s1), ahi[base + 1], alo[base + 1]);
        }
    }

    float C[8][4];
    // ---- layer 2 ----
#pragma unroll
    for (int j = 0; j < 8; j++) { C[j][0] = C[j][1] = C[j][2] = C[j][3] = 0.f; }
    gemm64(bHi0, bLo0, ahi, alo, lane, C);
#pragma unroll
    for (int j = 0; j < 8; j++) {
        const int base = (j >> 1) * 4 + (j & 1) * 2;
        packhl(act(C[j][0] * 0.125f), act(C[j][1] * 0.125f), ahi[base], alo[base]);
        packhl(act(C[j][2] * 0.125f), act(C[j][3] * 0.125f), ahi[base + 1], alo[base + 1]);
    }

    // ---- layer 3 ----
#pragma unroll
    for (int j = 0; j < 8; j++) { C[j][0] = C[j][1] = C[j][2] = C[j][3] = 0.f; }
    gemm64(bHi1, bLo1, ahi, alo, lane, C);
#pragma unroll
    for (int j = 0; j < 8; j++) {
        const int base = (j >> 1) * 4 + (j & 1) * 2;
        packhl(act(C[j][0] * 0.125f), act(C[j][1] * 0.125f), ahi[base], alo[base]);
        packhl(act(C[j][2] * 0.125f), act(C[j][3] * 0.125f), ahi[base + 1], alo[base + 1]);
    }

    __syncthreads();
    build_w4(Wm4, 0, bHi0, bLo0, t);
    build_w4(Wm4, 1, bHi1, bLo1, t);
    __syncthreads();

    // ---- layer 4 (8 paired chunks) + tensor product + scatter ----
    const float inv_sqrt3 = 0.5773502691896258f;
    const int eScat = w * 16 + (lane & 15);
    const int half = lane >> 4;
    const int snd = sSnd[eScat], rcv = sRcv[eScat];
    const float y0 = sY0[eScat];
    const float ya = sY1[eScat * 3], yb = sY1[eScat * 3 + 1], yc = sY1[eScat * 3 + 2];
    const int rowA = w * 16 + rl, rowB = rowA + 8;
    const float* tp = &sTP[eScat * 68 + half * 16];

    for (int q = 0; q < 8; q++) {
#pragma unroll
        for (int j = 0; j < 8; j++) { C[j][0] = C[j][1] = C[j][2] = C[j][3] = 0.f; }
        if (q & 1) gemm64(bHi1, bLo1, ahi, alo, lane, C);
        else       gemm64(bHi0, bLo0, ahi, alo, lane, C);

        // stage to warp-local sTP rows with the 1/sqrt(64) scale applied ONCE here
#pragma unroll
        for (int j = 0; j < 8; j++) {
            *(float2*)&sTP[rowA * 68 + 8 * j + cb] = make_float2(C[j][0] * 0.125f, C[j][1] * 0.125f);
            *(float2*)&sTP[rowB * 68 + 8 * j + cb] = make_float2(C[j][2] * 0.125f, C[j][3] * 0.125f);
        }
        __syncwarp();

        if (q < 4) {
            const int qch = 32 * q + half * 16;
#pragma unroll
            for (int jj = 0; jj < 16; jj += 4) {
                const float4 va = *(const float4*)(tp + jj);        // w1
                const float4 vb = *(const float4*)(tp + 32 + jj);   // w2
                const float4 s0 = *(const float4*)&g_ux0[snd * 128 + qch + jj];
                red4(&g_msg0[rcv * 256 + qch + jj],
                     va.x * s0.x * y0, va.y * s0.y * y0,
                     va.z * s0.z * y0, va.w * s0.w * y0);
                const float c0v = vb.x * s0.x, c1v = vb.y * s0.y;
                const float c2v = vb.z * s0.z, c3v = vb.w * s0.w;
                float* dst = &g_msg1[rcv * 768 + (qch + jj) * 3];
                red4(dst + 0, c0v * ya, c0v * yb, c0v * yc, c1v * ya);
                red4(dst + 4, c1v * yb, c1v * yc, c2v * ya, c2v * yb);
                red4(dst + 8, c2v * yc, c3v * ya, c3v * yb, c3v * yc);
            }
        } else {
            const int qch = 32 * (q - 4) + half * 16;
#pragma unroll
            for (int jj = 0; jj < 16; jj += 4) {
                const float4 va = *(const float4*)(tp + jj);        // w3
                const float4 vb = *(const float4*)(tp + 32 + jj);   // w4
                const float* s1 = &g_ux1[snd * 384 + (qch + jj) * 3];
                const float4 a = *(const float4*)(s1 + 0);
                const float4 b = *(const float4*)(s1 + 4);
                const float4 c = *(const float4*)(s1 + 8);
                float* dst = &g_msg1[rcv * 768 + 384 + (qch + jj) * 3];
                red4(dst + 0, va.x * a.x * y0, va.x * a.y * y0, va.x * a.z * y0, va.y * a.w * y0);
                red4(dst + 4, va.y * b.x * y0, va.y * b.y * y0, va.z * b.z * y0, va.z * b.w * y0);
                red4(dst + 8, va.z * c.x * y0, va.w * c.y * y0, va.w * c.z * y0, va.w * c.w * y0);
                const float d0 = a.x * ya + a.y * yb + a.z * yc;
                const float d1 = a.w * ya + b.x * yb + b.y * yc;
                const float d2 = b.z * ya + b.w * yb + c.x * yc;
                const float d3 = c.y * ya + c.z * yb + c.w * yc;
                red4(&g_msg0[rcv * 256 + 128 + qch + jj],
                     vb.x * d0 * inv_sqrt3, vb.y * d1 * inv_sqrt3,
                     vb.z * d2 * inv_sqrt3, vb.w * d3 * inv_sqrt3);
            }
        }

        __syncthreads();   // all warps done reading buf[q&1]; prior builds visible
        if (q < 6) {
            if (q & 1) build_w4(Wm4, q + 2, bHi1, bLo1, t);
            else       build_w4(Wm4, q + 2, bHi0, bLo0, t);
        }
    }
}

// ---------------- output linear (smem-staged weight chunks) ----------------
#define OUT_SMEM (98304)
__global__ __launch_bounds__(256) void out_kernel(const float* __restrict__ Wo0,
                                                  const float* __restrict__ Wo1,
                                                  float* __restrict__ out) {
    extern __shared__ float smo[];
    float* sX = smo;              // 16384 floats
    float* sW = smo + 16384;      // 8192 floats
    const int t = threadIdx.x;
    const int n0 = blockIdx.x * 16;
    for (int i = t; i < 16 * 1024; i += 256) {
        const int n = i >> 10, c = i & 1023;
        const int gn = n0 + n;
        sX[i] = (c < 256) ? g_msg0[gn * 256 + c] : g_msg1[gn * 768 + (c - 256)];
    }

    const int w = t >> 5, lane = t & 31;
    const int v0 = lane * 4;
    const float* xA = &sX[(2 * w) * 1024];
    const float* xB = &sX[(2 * w + 1) * 1024];

    float a0[2][4];
    float a1[2][4][3];
#pragma unroll
    for (int n = 0; n < 2; n++)
#pragma unroll
        for (int j = 0; j < 4; j++) {
            a0[n][j] = 0.f;
            a1[n][j][0] = 0.f; a1[n][j][1] = 0.f; a1[n][j][2] = 0.f;
        }

    for (int ci = 0; ci < 8; ci++) {
        const int u0 = ci * 32;
        __syncthreads();
        for (int i = t; i < 8192; i += 256) {
            int r = i >> 8, c = i & 255;
            sW[i] = (c < 128) ? Wo0[(u0 + r) * 128 + c] : Wo1[(u0 + r) * 128 + (c - 128)];
        }
        __syncthreads();
#pragma unroll 4
        for (int u = 0; u < 32; u++) {
            const float4 w0 = *(const float4*)&sW[u * 256 + v0];
            const float4 w1 = *(const float4*)&sW[u * 256 + 128 + v0];
            const float wv0[4] = {w0.x, w0.y, w0.z, w0.w};
            const float wv1[4] = {w1.x, w1.y, w1.z, w1.w};
            const int uu = u0 + u;
#pragma unroll
            for (int n = 0; n < 2; n++) {
                const float* x = n ? xB : xA;
                const float m0 = x[uu];
                const float ma = x[256 + uu * 3 + 0];
                const float mb = x[256 + uu * 3 + 1];
                const float mc = x[256 + uu * 3 + 2];
#pragma unroll
                for (int j = 0; j < 4; j++) {
                    a0[n][j] += m0 * wv0[j];
                    a1[n][j][0] += ma * wv1[j];
                    a1[n][j][1] += mb * wv1[j];
                    a1[n][j][2] += mc * wv1[j];
                }
            }
        }
    }

    const float s = 1.0f / 160.0f;  // (1/sqrt(256)) / AVG_NUM_NEIGHBORS
#pragma unroll
    for (int n = 0; n < 2; n++) {
        const int gn = n0 + 2 * w + n;
        float4 o0 = make_float4(a0[n][0] * s, a0[n][1] * s, a0[n][2] * s, a0[n][3] * s);
        *(float4*)&out[gn * 512 + v0] = o0;
        float* dst = &out[gn * 512 + 128 + v0 * 3];
        float4 p0 = make_float4(a1[n][0][0] * s, a1[n][0][1] * s, a1[n][0][2] * s, a1[n][1][0] * s);
        float4 p1 = make_float4(a1[n][1][1] * s, a1[n][1][2] * s, a1[n][2][0] * s, a1[n][2][1] * s);
        float4 p2 = make_float4(a1[n][2][2] * s, a1[n][3][0] * s, a1[n][3][1] * s, a1[n][3][2] * s);
        *(float4*)(dst + 0) = p0;
        *(float4*)(dst + 4) = p1;
        *(float4*)(dst + 8) = p2;
    }
}

// ---------------- launch ----------------
extern "C" void kernel_launch(void* const* d_in, const int* in_sizes, int n_in,
                              void* d_out, int out_size) {
    const float* nf  = (const float*)d_in[0];
    const float* ea  = (const float*)d_in[1];
    const float* ef  = (const float*)d_in[2];
    const int*   ei  = (const int*)d_in[3];
    const float* Wu0 = (const float*)d_in[4];
    const float* Wu1 = (const float*)d_in[5];
    const float* Wm1 = (const float*)d_in[6];
    const float* Wm2 = (const float*)d_in[7];
    const float* Wm3 = (const float*)d_in[8];
    const float* Wm4 = (const float*)d_in[9];
    const float* Wo0 = (const float*)d_in[10];
    const float* Wo1 = (const float*)d_in[11];
    float* out = (float*)d_out;

    cudaFuncSetAttribute(edge_kernel, cudaFuncAttributeMaxDynamicSharedMemorySize, EDGE_SMEM);
    cudaFuncSetAttribute(out_kernel, cudaFuncAttributeMaxDynamicSharedMemorySize, OUT_SMEM);
    cudaFuncSetAttribute(up_kernel, cudaFuncAttributeMaxDynamicSharedMemorySize, UP_SMEM);

    zero_kernel<<<10000, 256>>>();
    up_kernel<<<625, 256, UP_SMEM>>>(nf, Wu0, Wu1);
    edge_kernel<<<1250, 256, EDGE_SMEM>>>(ea, ef, ei, Wm1, Wm2, Wm3, Wm4);
    out_kernel<<<625, 256, OUT_SMEM>>>(Wo0, Wo1, out);
}